// round 3
// baseline (speedup 1.0000x reference)
#include <cuda_runtime.h>

#define N_NODES 50000
#define N_EDGES 800000
#define H 64
#define RES 0.5f
#define INV_1PRES (1.0f / (1.0f + RES))
#define SCAN_THREADS 1024
#define SCAN_CHUNK 49                     // 1024*49 = 50176 >= N_NODES
#define N_PAD (SCAN_THREADS * SCAN_CHUNK)

// ---------------- device scratch (no allocation allowed) ----------------
__device__ float  g_s1[N_NODES];
__device__ float  g_s2[N_NODES];          // att_b folded in
__device__ int    g_deg[N_PAD];
__device__ int    g_off[N_PAD];
__device__ int    g_pos[N_PAD];
__device__ float4 g_pack[N_EDGES];        // {exp_att, adj*RES/(1+RES), col, eid}

typedef unsigned long long u64;

__device__ __forceinline__ u64 pack2(float lo, float hi) {
    u64 r;
    asm("mov.b64 %0, {%1, %2};" : "=l"(r) : "f"(lo), "f"(hi));
    return r;
}
__device__ __forceinline__ void unpack2(u64 v, float& lo, float& hi) {
    asm("mov.b64 {%0, %1}, %2;" : "=f"(lo), "=f"(hi) : "l"(v));
}
__device__ __forceinline__ u64 ffma2(u64 a, u64 b, u64 c) {
    u64 d;
    asm("fma.rn.f32x2 %0, %1, %2, %3;" : "=l"(d) : "l"(a), "l"(b), "l"(c));
    return d;
}

// ------------------------------------------------------------------------
// Kernel 1: tiled dual-GEMM for per-node attention scalars + zero g_deg.
//   Block(256) handles a 64-node tile. Thread (ng=tid&31, cg=tid>>5):
//   2 nodes x 8 cols x 2 mats in f32x2 regs. cg uniform per warp -> weight
//   LDS fully broadcast.
// ------------------------------------------------------------------------
__global__ __launch_bounds__(256)
void gat_node_kernel(const float* __restrict__ embeds,
                     const float* __restrict__ W1, const float* __restrict__ b1,
                     const float* __restrict__ W2, const float* __restrict__ b2,
                     const float* __restrict__ att_w, const float* __restrict__ att_b) {
    __shared__ float Xs[64 * 64];    // k-major: Xs[k*64 + node_local]
    __shared__ float W1s[64 * 64];   // row-major: W1s[k*64 + j]
    __shared__ float W2s[64 * 64];

    const int tid = threadIdx.x;
    const int tile = blockIdx.x * 64;
    const int ng = tid & 31;   // nodes 2*ng, 2*ng+1
    const int cg = tid >> 5;   // cols cg*8 .. cg*8+7 (uniform per warp)

    // zero degree histogram (re-done every replay)
    {
        int gid = blockIdx.x * 256 + tid;
        if (gid < N_PAD) g_deg[gid] = 0;
    }

    // ---- load W1, W2 (coalesced float4 copies) ----
    {
        const float4* w1g = (const float4*)W1;
        const float4* w2g = (const float4*)W2;
        float4* w1s = (float4*)W1s;
        float4* w2s = (float4*)W2s;
#pragma unroll
        for (int i = 0; i < 4; i++) {
            int idx = tid + i * 256;
            w1s[idx] = w1g[idx];
            w2s[idx] = w2g[idx];
        }
    }
    // ---- load X tile, transpose to k-major ----
    {
        const float4* xg = (const float4*)embeds;
#pragma unroll
        for (int i = 0; i < 4; i++) {
            int idx = tid + i * 256;          // [0,1024)
            int nl = idx >> 4;                // node local 0..63
            int k4 = idx & 15;                // float4 index within row
            int node = tile + nl;
            if (node > N_NODES - 1) node = N_NODES - 1;
            float4 v = xg[(size_t)node * 16 + k4];
            Xs[(4 * k4 + 0) * 64 + nl] = v.x;
            Xs[(4 * k4 + 1) * 64 + nl] = v.y;
            Xs[(4 * k4 + 2) * 64 + nl] = v.z;
            Xs[(4 * k4 + 3) * 64 + nl] = v.w;
        }
    }
    __syncthreads();

    // ---- main loop: 16 f32x2 accumulators ----
    u64 acc1[2][4], acc2[2][4];
#pragma unroll
    for (int n = 0; n < 2; n++)
#pragma unroll
        for (int j = 0; j < 4; j++) { acc1[n][j] = 0ULL; acc2[n][j] = 0ULL; }

#pragma unroll 4
    for (int k = 0; k < 64; k++) {
        float2 xv = *(const float2*)(Xs + k * 64 + ng * 2);
        u64 xp0 = pack2(xv.x, xv.x);
        u64 xp1 = pack2(xv.y, xv.y);
        const float* w1r = W1s + k * 64 + cg * 8;
        const float* w2r = W2s + k * 64 + cg * 8;
        ulonglong2 w1a = *(const ulonglong2*)(w1r);
        ulonglong2 w1b = *(const ulonglong2*)(w1r + 4);
        ulonglong2 w2a = *(const ulonglong2*)(w2r);
        ulonglong2 w2b = *(const ulonglong2*)(w2r + 4);
        acc1[0][0] = ffma2(xp0, w1a.x, acc1[0][0]);
        acc1[0][1] = ffma2(xp0, w1a.y, acc1[0][1]);
        acc1[0][2] = ffma2(xp0, w1b.x, acc1[0][2]);
        acc1[0][3] = ffma2(xp0, w1b.y, acc1[0][3]);
        acc2[0][0] = ffma2(xp0, w2a.x, acc2[0][0]);
        acc2[0][1] = ffma2(xp0, w2a.y, acc2[0][1]);
        acc2[0][2] = ffma2(xp0, w2b.x, acc2[0][2]);
        acc2[0][3] = ffma2(xp0, w2b.y, acc2[0][3]);
        acc1[1][0] = ffma2(xp1, w1a.x, acc1[1][0]);
        acc1[1][1] = ffma2(xp1, w1a.y, acc1[1][1]);
        acc1[1][2] = ffma2(xp1, w1b.x, acc1[1][2]);
        acc1[1][3] = ffma2(xp1, w1b.y, acc1[1][3]);
        acc2[1][0] = ffma2(xp1, w2a.x, acc2[1][0]);
        acc2[1][1] = ffma2(xp1, w2a.y, acc2[1][1]);
        acc2[1][2] = ffma2(xp1, w2b.x, acc2[1][2]);
        acc2[1][3] = ffma2(xp1, w2b.y, acc2[1][3]);
    }

    // ---- epilogue: bias + relu + att_w dot over this thread's 8 cols ----
    float b1v[8], b2v[8], aw1[8], aw2[8];
    {
        float4 t;
        t = __ldg((const float4*)(b1 + cg * 8));     b1v[0]=t.x;b1v[1]=t.y;b1v[2]=t.z;b1v[3]=t.w;
        t = __ldg((const float4*)(b1 + cg * 8 + 4)); b1v[4]=t.x;b1v[5]=t.y;b1v[6]=t.z;b1v[7]=t.w;
        t = __ldg((const float4*)(b2 + cg * 8));     b2v[0]=t.x;b2v[1]=t.y;b2v[2]=t.z;b2v[3]=t.w;
        t = __ldg((const float4*)(b2 + cg * 8 + 4)); b2v[4]=t.x;b2v[5]=t.y;b2v[6]=t.z;b2v[7]=t.w;
        t = __ldg((const float4*)(att_w + cg * 8));      aw1[0]=t.x;aw1[1]=t.y;aw1[2]=t.z;aw1[3]=t.w;
        t = __ldg((const float4*)(att_w + cg * 8 + 4));  aw1[4]=t.x;aw1[5]=t.y;aw1[6]=t.z;aw1[7]=t.w;
        t = __ldg((const float4*)(att_w + H + cg * 8));     aw2[0]=t.x;aw2[1]=t.y;aw2[2]=t.z;aw2[3]=t.w;
        t = __ldg((const float4*)(att_w + H + cg * 8 + 4)); aw2[4]=t.x;aw2[5]=t.y;aw2[6]=t.z;aw2[7]=t.w;
    }

    float p1[2], p2[2];
#pragma unroll
    for (int n = 0; n < 2; n++) {
        float s1 = 0.f, s2 = 0.f;
#pragma unroll
        for (int j = 0; j < 4; j++) {
            float a, b;
            unpack2(acc1[n][j], a, b);
            s1 += fmaxf(a + b1v[2 * j], 0.f) * aw1[2 * j]
                + fmaxf(b + b1v[2 * j + 1], 0.f) * aw1[2 * j + 1];
            unpack2(acc2[n][j], a, b);
            s2 += fmaxf(a + b2v[2 * j], 0.f) * aw2[2 * j]
                + fmaxf(b + b2v[2 * j + 1], 0.f) * aw2[2 * j + 1];
        }
        p1[n] = s1;
        p2[n] = s2;
    }

    // ---- cross-colgroup reduction via smem (reuse Xs) ----
    __syncthreads();
    float* red1 = Xs;          // [64 nodes][8 cg]
    float* red2 = Xs + 512;
#pragma unroll
    for (int n = 0; n < 2; n++) {
        int nl = ng * 2 + n;
        red1[nl * 8 + cg] = p1[n];
        red2[nl * 8 + cg] = p2[n];
    }
    __syncthreads();

    if (tid < 64) {
        int node = tile + tid;
        if (node < N_NODES) {
            float s1 = 0.f, s2 = 0.f;
#pragma unroll
            for (int c = 0; c < 8; c++) { s1 += red1[tid * 8 + c]; s2 += red2[tid * 8 + c]; }
            g_s1[node] = s1;
            g_s2[node] = s2 + __ldg(att_b);
        }
    }
}

// ------------------------------------------------------------------------
// Kernel 2a: degree histogram
// ------------------------------------------------------------------------
__global__ __launch_bounds__(256)
void gat_hist_kernel(const int* __restrict__ edge_index) {
    int e = blockIdx.x * blockDim.x + threadIdx.x;
    if (e >= N_EDGES) return;
    atomicAdd(&g_deg[edge_index[e]], 1);
}

// ------------------------------------------------------------------------
// Kernel 2b: exclusive scan of degrees (single block)
// ------------------------------------------------------------------------
__global__ __launch_bounds__(SCAN_THREADS)
void gat_scan_kernel() {
    __shared__ int sums[SCAN_THREADS];
    const int t = threadIdx.x;
    const int base = t * SCAN_CHUNK;

    int s = 0;
#pragma unroll
    for (int i = 0; i < SCAN_CHUNK; i++) s += g_deg[base + i];
    sums[t] = s;
    __syncthreads();

    // Hillis-Steele inclusive scan
    for (int off = 1; off < SCAN_THREADS; off <<= 1) {
        int v = (t >= off) ? sums[t - off] : 0;
        __syncthreads();
        sums[t] += v;
        __syncthreads();
    }

    int run = sums[t] - s;   // exclusive prefix of this chunk
#pragma unroll
    for (int i = 0; i < SCAN_CHUNK; i++) {
        int idx = base + i;
        g_off[idx] = run;
        g_pos[idx] = run;
        run += g_deg[idx];
    }
}

// ------------------------------------------------------------------------
// Kernel 2c: per-edge exp(att) + scatter packed record into CSR slot
// ------------------------------------------------------------------------
__global__ __launch_bounds__(256)
void gat_scatter_kernel(const int* __restrict__ edge_index,
                        const float* __restrict__ adj_values) {
    int e = blockIdx.x * blockDim.x + threadIdx.x;
    if (e >= N_EDGES) return;
    int r = edge_index[e];
    int c = edge_index[N_EDGES + e];
    float ea = __expf(g_s1[r] + g_s2[c]);
    int p = atomicAdd(&g_pos[r], 1);
    float4 pk;
    pk.x = ea;
    pk.y = adj_values[e] * (RES * INV_1PRES);
    pk.z = __int_as_float(c);
    pk.w = __int_as_float(e);
    g_pack[p] = pk;
}

// ------------------------------------------------------------------------
// Kernel 3: warp-per-row — rowsum, values, and SpMM row accumulate.
// Output row written exactly once (no atomics).
// ------------------------------------------------------------------------
__global__ __launch_bounds__(256)
void gat_row_kernel(const float* __restrict__ embeds,
                    float* __restrict__ values,
                    float* __restrict__ out_part) {
    const unsigned FULL = 0xffffffffu;
    int w = (blockIdx.x * blockDim.x + threadIdx.x) >> 5;
    if (w >= N_NODES) return;
    int lane = threadIdx.x & 31;

    int off = g_off[w];
    int deg = g_deg[w];

    // pass 1: rowsum of exp_att
    float s = 0.f;
    for (int j = lane; j < deg; j += 32) s += g_pack[off + j].x;
#pragma unroll
    for (int m = 16; m > 0; m >>= 1) s += __shfl_xor_sync(FULL, s, m);
    float vscale = INV_1PRES / (s + 1e-6f);

    // pass 2: values + row accumulate
    float2 acc = make_float2(0.f, 0.f);
    for (int base = 0; base < deg; base += 32) {
        int j = base + lane;
        int cnt = deg - base; if (cnt > 32) cnt = 32;
        float ea = 0.f, radj = 0.f;
        int c = 0;
        if (j < deg) {
            float4 pk = g_pack[off + j];
            ea = pk.x; radj = pk.y;
            c = __float_as_int(pk.z);
            int eid = __float_as_int(pk.w);
            values[eid] = fmaf(ea, vscale, radj);
        }
        float v = fmaf(ea, vscale, radj);
        for (int q = 0; q < cnt; q++) {
            float vq = __shfl_sync(FULL, v, q);
            int   cq = __shfl_sync(FULL, c, q);
            float2 ev = *(const float2*)(embeds + (size_t)cq * H + lane * 2);
            acc.x = fmaf(vq, ev.x, acc.x);
            acc.y = fmaf(vq, ev.y, acc.y);
        }
    }
    *(float2*)(out_part + (size_t)w * H + lane * 2) = acc;
}

// ------------------------------------------------------------------------
extern "C" void kernel_launch(void* const* d_in, const int* in_sizes, int n_in,
                              void* d_out, int out_size) {
    const int*   edge_index = (const int*)d_in[0];
    const float* adj_values = (const float*)d_in[1];
    const float* embeds     = (const float*)d_in[2];
    const float* W1         = (const float*)d_in[3];
    const float* b1         = (const float*)d_in[4];
    const float* W2         = (const float*)d_in[5];
    const float* b2         = (const float*)d_in[6];
    const float* att_w      = (const float*)d_in[7];
    const float* att_b      = (const float*)d_in[8];

    float* values   = (float*)d_out;            // [E]
    float* out_part = (float*)d_out + N_EDGES;  // [N, H]

    gat_node_kernel<<<(N_NODES + 63) / 64, 256>>>(
        embeds, W1, b1, W2, b2, att_w, att_b);

    gat_hist_kernel<<<(N_EDGES + 255) / 256, 256>>>(edge_index);

    gat_scan_kernel<<<1, SCAN_THREADS>>>();

    gat_scatter_kernel<<<(N_EDGES + 255) / 256, 256>>>(edge_index, adj_values);

    gat_row_kernel<<<(N_NODES * 32 + 255) / 256, 256>>>(embeds, values, out_part);
}

// round 4
// speedup vs baseline: 1.6050x; 1.6050x over previous
#include <cuda_runtime.h>

#define N_NODES 50000
#define N_EDGES 800000
#define H 64
#define RES 0.5f
#define INV_1PRES (1.0f / (1.0f + RES))

// ---------------- device scratch (no allocation allowed) ----------------
__device__ float g_s1[N_NODES];
__device__ float g_s2[N_NODES];      // att_b folded in
__device__ float g_rowsum[N_NODES];
__device__ float g_expatt[N_EDGES];

typedef unsigned long long u64;

__device__ __forceinline__ u64 pack2(float lo, float hi) {
    u64 r;
    asm("mov.b64 %0, {%1, %2};" : "=l"(r) : "f"(lo), "f"(hi));
    return r;
}
__device__ __forceinline__ void unpack2(u64 v, float& lo, float& hi) {
    asm("mov.b64 {%0, %1}, %2;" : "=f"(lo), "=f"(hi) : "l"(v));
}
__device__ __forceinline__ u64 ffma2(u64 a, u64 b, u64 c) {
    u64 d;
    asm("fma.rn.f32x2 %0, %1, %2, %3;" : "=l"(d) : "l"(a), "l"(b), "l"(c));
    return d;
}

// ------------------------------------------------------------------------
// Kernel 1: tiled dual-GEMM for per-node attention scalars.
//   Block(256) handles a 64-node tile. Thread (ng=tid&31, cg=tid>>5):
//   2 nodes x 8 cols x 2 mats in f32x2 regs. cg uniform per warp -> weight
//   LDS fully broadcast. Also zeroes g_rowsum and the output SpMM region.
// ------------------------------------------------------------------------
__global__ __launch_bounds__(256)
void gat_node_kernel(const float* __restrict__ embeds,
                     const float* __restrict__ W1, const float* __restrict__ b1,
                     const float* __restrict__ W2, const float* __restrict__ b2,
                     const float* __restrict__ att_w, const float* __restrict__ att_b,
                     float* __restrict__ out_part) {
    __shared__ float Xs[64 * 64];    // k-major: Xs[k*64 + node_local]
    __shared__ float W1s[64 * 64];   // row-major: W1s[k*64 + j]
    __shared__ float W2s[64 * 64];

    const int tid = threadIdx.x;
    const int tile = blockIdx.x * 64;
    const int ng = tid & 31;   // nodes 2*ng, 2*ng+1
    const int cg = tid >> 5;   // cols cg*8 .. cg*8+7 (uniform per warp)

    // ---- load W1, W2 (coalesced float4 copies) ----
    {
        const float4* w1g = (const float4*)W1;
        const float4* w2g = (const float4*)W2;
        float4* w1s = (float4*)W1s;
        float4* w2s = (float4*)W2s;
#pragma unroll
        for (int i = 0; i < 4; i++) {
            int idx = tid + i * 256;
            w1s[idx] = w1g[idx];
            w2s[idx] = w2g[idx];
        }
    }
    // ---- load X tile, transpose to k-major ----
    {
        const float4* xg = (const float4*)embeds;
#pragma unroll
        for (int i = 0; i < 4; i++) {
            int idx = tid + i * 256;          // [0,1024)
            int nl = idx >> 4;                // node local 0..63
            int k4 = idx & 15;                // float4 index within row
            int node = tile + nl;
            if (node > N_NODES - 1) node = N_NODES - 1;
            float4 v = xg[(size_t)node * 16 + k4];
            Xs[(4 * k4 + 0) * 64 + nl] = v.x;
            Xs[(4 * k4 + 1) * 64 + nl] = v.y;
            Xs[(4 * k4 + 2) * 64 + nl] = v.z;
            Xs[(4 * k4 + 3) * 64 + nl] = v.w;
        }
    }
    __syncthreads();

    // ---- main loop: 16 f32x2 accumulators ----
    u64 acc1[2][4], acc2[2][4];
#pragma unroll
    for (int n = 0; n < 2; n++)
#pragma unroll
        for (int j = 0; j < 4; j++) { acc1[n][j] = 0ULL; acc2[n][j] = 0ULL; }

#pragma unroll 4
    for (int k = 0; k < 64; k++) {
        float2 xv = *(const float2*)(Xs + k * 64 + ng * 2);
        u64 xp0 = pack2(xv.x, xv.x);
        u64 xp1 = pack2(xv.y, xv.y);
        const float* w1r = W1s + k * 64 + cg * 8;
        const float* w2r = W2s + k * 64 + cg * 8;
        ulonglong2 w1a = *(const ulonglong2*)(w1r);
        ulonglong2 w1b = *(const ulonglong2*)(w1r + 4);
        ulonglong2 w2a = *(const ulonglong2*)(w2r);
        ulonglong2 w2b = *(const ulonglong2*)(w2r + 4);
        acc1[0][0] = ffma2(xp0, w1a.x, acc1[0][0]);
        acc1[0][1] = ffma2(xp0, w1a.y, acc1[0][1]);
        acc1[0][2] = ffma2(xp0, w1b.x, acc1[0][2]);
        acc1[0][3] = ffma2(xp0, w1b.y, acc1[0][3]);
        acc2[0][0] = ffma2(xp0, w2a.x, acc2[0][0]);
        acc2[0][1] = ffma2(xp0, w2a.y, acc2[0][1]);
        acc2[0][2] = ffma2(xp0, w2b.x, acc2[0][2]);
        acc2[0][3] = ffma2(xp0, w2b.y, acc2[0][3]);
        acc1[1][0] = ffma2(xp1, w1a.x, acc1[1][0]);
        acc1[1][1] = ffma2(xp1, w1a.y, acc1[1][1]);
        acc1[1][2] = ffma2(xp1, w1b.x, acc1[1][2]);
        acc1[1][3] = ffma2(xp1, w1b.y, acc1[1][3]);
        acc2[1][0] = ffma2(xp1, w2a.x, acc2[1][0]);
        acc2[1][1] = ffma2(xp1, w2a.y, acc2[1][1]);
        acc2[1][2] = ffma2(xp1, w2b.x, acc2[1][2]);
        acc2[1][3] = ffma2(xp1, w2b.y, acc2[1][3]);
    }

    // ---- epilogue: bias + relu + att_w dot over this thread's 8 cols ----
    float b1v[8], b2v[8], aw1[8], aw2[8];
    {
        float4 t;
        t = __ldg((const float4*)(b1 + cg * 8));     b1v[0]=t.x;b1v[1]=t.y;b1v[2]=t.z;b1v[3]=t.w;
        t = __ldg((const float4*)(b1 + cg * 8 + 4)); b1v[4]=t.x;b1v[5]=t.y;b1v[6]=t.z;b1v[7]=t.w;
        t = __ldg((const float4*)(b2 + cg * 8));     b2v[0]=t.x;b2v[1]=t.y;b2v[2]=t.z;b2v[3]=t.w;
        t = __ldg((const float4*)(b2 + cg * 8 + 4)); b2v[4]=t.x;b2v[5]=t.y;b2v[6]=t.z;b2v[7]=t.w;
        t = __ldg((const float4*)(att_w + cg * 8));      aw1[0]=t.x;aw1[1]=t.y;aw1[2]=t.z;aw1[3]=t.w;
        t = __ldg((const float4*)(att_w + cg * 8 + 4));  aw1[4]=t.x;aw1[5]=t.y;aw1[6]=t.z;aw1[7]=t.w;
        t = __ldg((const float4*)(att_w + H + cg * 8));     aw2[0]=t.x;aw2[1]=t.y;aw2[2]=t.z;aw2[3]=t.w;
        t = __ldg((const float4*)(att_w + H + cg * 8 + 4)); aw2[4]=t.x;aw2[5]=t.y;aw2[6]=t.z;aw2[7]=t.w;
    }

    float p1[2], p2[2];
#pragma unroll
    for (int n = 0; n < 2; n++) {
        float s1 = 0.f, s2 = 0.f;
#pragma unroll
        for (int j = 0; j < 4; j++) {
            float a, b;
            unpack2(acc1[n][j], a, b);
            s1 += fmaxf(a + b1v[2 * j], 0.f) * aw1[2 * j]
                + fmaxf(b + b1v[2 * j + 1], 0.f) * aw1[2 * j + 1];
            unpack2(acc2[n][j], a, b);
            s2 += fmaxf(a + b2v[2 * j], 0.f) * aw2[2 * j]
                + fmaxf(b + b2v[2 * j + 1], 0.f) * aw2[2 * j + 1];
        }
        p1[n] = s1;
        p2[n] = s2;
    }

    // ---- cross-colgroup reduction via smem (reuse Xs) ----
    __syncthreads();
    float* red1 = Xs;          // [64 nodes][8 cg]
    float* red2 = Xs + 512;
#pragma unroll
    for (int n = 0; n < 2; n++) {
        int nl = ng * 2 + n;
        red1[nl * 8 + cg] = p1[n];
        red2[nl * 8 + cg] = p2[n];
    }
    __syncthreads();

    if (tid < 64) {
        int node = tile + tid;
        if (node < N_NODES) {
            float s1 = 0.f, s2 = 0.f;
#pragma unroll
            for (int c = 0; c < 8; c++) { s1 += red1[tid * 8 + c]; s2 += red2[tid * 8 + c]; }
            g_s1[node] = s1;
            g_s2[node] = s2 + __ldg(att_b);
            g_rowsum[node] = 0.f;
        }
    }

    // ---- zero output SpMM region (d_out is poisoned) ----
    {
        float4 z = make_float4(0.f, 0.f, 0.f, 0.f);
        float4* op = (float4*)(out_part + (size_t)tile * H);
        int lim = N_NODES - tile;          // nodes valid in this tile
        if (lim > 64) lim = 64;
        int lim4 = lim * 16;               // float4s valid
#pragma unroll
        for (int i = 0; i < 4; i++) {
            int idx = tid + i * 256;
            if (idx < lim4) op[idx] = z;
        }
    }
}

// ------------------------------------------------------------------------
// Kernel 2: per-edge exp(att) + segment-sum of denominators
// ------------------------------------------------------------------------
__global__ __launch_bounds__(256)
void gat_edge_att_kernel(const int* __restrict__ edge_index) {
    int e = blockIdx.x * blockDim.x + threadIdx.x;
    if (e >= N_EDGES) return;
    int r = __ldg(edge_index + e);
    int c = __ldg(edge_index + N_EDGES + e);
    float ea = __expf(__ldg(g_s1 + r) + __ldg(g_s2 + c));
    g_expatt[e] = ea;
    atomicAdd(&g_rowsum[r], ea);
}

// ------------------------------------------------------------------------
// Kernel 3: per-edge value + SpMM scatter (16 threads per edge, float4 red)
// ------------------------------------------------------------------------
__global__ __launch_bounds__(256)
void gat_edge_spmm_kernel(const int* __restrict__ edge_index,
                          const float* __restrict__ adj_values,
                          const float* __restrict__ embeds,
                          float* __restrict__ values,
                          float* __restrict__ out_part) {
    unsigned gid = blockIdx.x * blockDim.x + threadIdx.x;
    unsigned e = gid >> 4;
    if (e >= N_EDGES) return;
    unsigned lane = threadIdx.x & 31u;
    unsigned sub = gid & 15u;

    int r = 0, c = 0;
    float v = 0.f;
    if (sub == 0) {
        r = __ldg(edge_index + e);
        c = __ldg(edge_index + N_EDGES + e);
        float ea = g_expatt[e];
        float rs = g_rowsum[r] + 1e-6f;
        v = (ea / rs + RES * __ldg(adj_values + e)) * INV_1PRES;
        values[e] = v;
    }
    unsigned base = lane & 16u;  // leader lane of this 16-thread group
    v = __shfl_sync(0xffffffffu, v, base);
    r = __shfl_sync(0xffffffffu, r, base);
    c = __shfl_sync(0xffffffffu, c, base);

    float4 ev = __ldg((const float4*)(embeds + (size_t)c * H + sub * 4));
    float* dst = out_part + (size_t)r * H + sub * 4;
    asm volatile("red.global.add.v4.f32 [%0], {%1, %2, %3, %4};"
                 :: "l"(dst), "f"(ev.x * v), "f"(ev.y * v), "f"(ev.z * v), "f"(ev.w * v)
                 : "memory");
}

// ------------------------------------------------------------------------
extern "C" void kernel_launch(void* const* d_in, const int* in_sizes, int n_in,
                              void* d_out, int out_size) {
    const int*   edge_index = (const int*)d_in[0];
    const float* adj_values = (const float*)d_in[1];
    const float* embeds     = (const float*)d_in[2];
    const float* W1         = (const float*)d_in[3];
    const float* b1         = (const float*)d_in[4];
    const float* W2         = (const float*)d_in[5];
    const float* b2         = (const float*)d_in[6];
    const float* att_w      = (const float*)d_in[7];
    const float* att_b      = (const float*)d_in[8];

    float* values   = (float*)d_out;            // [E]
    float* out_part = (float*)d_out + N_EDGES;  // [N, H]

    gat_node_kernel<<<(N_NODES + 63) / 64, 256>>>(
        embeds, W1, b1, W2, b2, att_w, att_b, out_part);

    gat_edge_att_kernel<<<(N_EDGES + 255) / 256, 256>>>(edge_index);

    gat_edge_spmm_kernel<<<(N_EDGES * 16 + 255) / 256, 256>>>(
        edge_index, adj_values, embeds, values, out_part);
}

// round 5
// speedup vs baseline: 1.7990x; 1.1209x over previous
#include <cuda_runtime.h>

#define N_NODES 50000
#define N_EDGES 800000
#define H 64
#define RES 0.5f
#define INV_1PRES (1.0f / (1.0f + RES))

// ---------------- device scratch (no allocation allowed) ----------------
__device__ float g_s1[N_NODES];
__device__ float g_s2[N_NODES];      // att_b folded in
__device__ float g_rowsum[N_NODES];
__device__ float g_expatt[N_EDGES];

typedef unsigned long long u64;

__device__ __forceinline__ u64 pack2(float lo, float hi) {
    u64 r;
    asm("mov.b64 %0, {%1, %2};" : "=l"(r) : "f"(lo), "f"(hi));
    return r;
}
__device__ __forceinline__ void unpack2(u64 v, float& lo, float& hi) {
    asm("mov.b64 {%0, %1}, %2;" : "=f"(lo), "=f"(hi) : "l"(v));
}
__device__ __forceinline__ u64 ffma2(u64 a, u64 b, u64 c) {
    u64 d;
    asm("fma.rn.f32x2 %0, %1, %2, %3;" : "=l"(d) : "l"(a), "l"(b), "l"(c));
    return d;
}

// ------------------------------------------------------------------------
// Kernel 1: tiled dual-GEMM for per-node attention scalars.
//   Block(256) handles a 128-node tile. Thread (ng=tid&31, cg=tid>>5):
//   4 nodes x 8 cols x 2 mats in f32x2 regs (32 accumulators).
//   Conflict-free smem transpose: consecutive lanes own consecutive nodes,
//   so STS during the transpose is row-coalesced (no 16-way bank conflict).
//   Weight LDS are warp-uniform broadcasts. Dynamic smem = 64KB.
// ------------------------------------------------------------------------
__global__ __launch_bounds__(256, 2)
void gat_node_kernel(const float* __restrict__ embeds,
                     const float* __restrict__ W1, const float* __restrict__ b1,
                     const float* __restrict__ W2, const float* __restrict__ b2,
                     const float* __restrict__ att_w, const float* __restrict__ att_b,
                     float* __restrict__ out_part) {
    extern __shared__ float smem[];
    float* Xs  = smem;            // [64 k][128 nodes]  = 8192 floats (32KB)
    float* W1s = smem + 8192;     // [64 k][64 j]       = 4096 floats (16KB)
    float* W2s = smem + 12288;    // 16KB

    const int tid = threadIdx.x;
    const int tile = blockIdx.x * 128;
    const int ng = tid & 31;   // nodes 4*ng .. 4*ng+3
    const int cg = tid >> 5;   // cols cg*8 .. cg*8+7 (uniform per warp)

    // ---- load W1, W2 (coalesced float4 copies) ----
    {
        const float4* w1g = (const float4*)W1;
        const float4* w2g = (const float4*)W2;
        float4* w1s = (float4*)W1s;
        float4* w2s = (float4*)W2s;
#pragma unroll
        for (int i = 0; i < 4; i++) {
            int idx = tid + i * 256;
            w1s[idx] = w1g[idx];
            w2s[idx] = w2g[idx];
        }
    }
    // ---- load X tile -> k-major smem, conflict-free STS ----
    // idx layout: nl = idx & 127 (consecutive lanes = consecutive nodes),
    //             k4 = idx >> 7  (float4 chunk of the k dimension).
    {
#pragma unroll
        for (int i = 0; i < 8; i++) {
            int idx = tid + i * 256;          // [0, 2048)
            int nl = idx & 127;
            int k4 = idx >> 7;                // 0..15
            int node = tile + nl;
            if (node > N_NODES - 1) node = N_NODES - 1;
            float4 v = __ldg((const float4*)(embeds + (size_t)node * H + k4 * 4));
            Xs[(4 * k4 + 0) * 128 + nl] = v.x;   // lanes write consecutive cols
            Xs[(4 * k4 + 1) * 128 + nl] = v.y;
            Xs[(4 * k4 + 2) * 128 + nl] = v.z;
            Xs[(4 * k4 + 3) * 128 + nl] = v.w;
        }
    }
    __syncthreads();

    // ---- main loop: 32 f32x2 accumulators ----
    u64 acc1[4][4], acc2[4][4];
#pragma unroll
    for (int n = 0; n < 4; n++)
#pragma unroll
        for (int j = 0; j < 4; j++) { acc1[n][j] = 0ULL; acc2[n][j] = 0ULL; }

#pragma unroll 4
    for (int k = 0; k < 64; k++) {
        float4 xv = *(const float4*)(Xs + k * 128 + ng * 4);
        u64 xp[4];
        xp[0] = pack2(xv.x, xv.x);
        xp[1] = pack2(xv.y, xv.y);
        xp[2] = pack2(xv.z, xv.z);
        xp[3] = pack2(xv.w, xv.w);
        const float* w1r = W1s + k * 64 + cg * 8;   // warp-uniform (broadcast)
        const float* w2r = W2s + k * 64 + cg * 8;
        ulonglong2 w1a = *(const ulonglong2*)(w1r);
        ulonglong2 w1b = *(const ulonglong2*)(w1r + 4);
        ulonglong2 w2a = *(const ulonglong2*)(w2r);
        ulonglong2 w2b = *(const ulonglong2*)(w2r + 4);
#pragma unroll
        for (int n = 0; n < 4; n++) {
            acc1[n][0] = ffma2(xp[n], w1a.x, acc1[n][0]);
            acc1[n][1] = ffma2(xp[n], w1a.y, acc1[n][1]);
            acc1[n][2] = ffma2(xp[n], w1b.x, acc1[n][2]);
            acc1[n][3] = ffma2(xp[n], w1b.y, acc1[n][3]);
            acc2[n][0] = ffma2(xp[n], w2a.x, acc2[n][0]);
            acc2[n][1] = ffma2(xp[n], w2a.y, acc2[n][1]);
            acc2[n][2] = ffma2(xp[n], w2b.x, acc2[n][2]);
            acc2[n][3] = ffma2(xp[n], w2b.y, acc2[n][3]);
        }
    }

    // ---- epilogue: bias + relu + att_w dot over this thread's 8 cols ----
    float b1v[8], b2v[8], aw1[8], aw2[8];
    {
        float4 t;
        t = __ldg((const float4*)(b1 + cg * 8));     b1v[0]=t.x;b1v[1]=t.y;b1v[2]=t.z;b1v[3]=t.w;
        t = __ldg((const float4*)(b1 + cg * 8 + 4)); b1v[4]=t.x;b1v[5]=t.y;b1v[6]=t.z;b1v[7]=t.w;
        t = __ldg((const float4*)(b2 + cg * 8));     b2v[0]=t.x;b2v[1]=t.y;b2v[2]=t.z;b2v[3]=t.w;
        t = __ldg((const float4*)(b2 + cg * 8 + 4)); b2v[4]=t.x;b2v[5]=t.y;b2v[6]=t.z;b2v[7]=t.w;
        t = __ldg((const float4*)(att_w + cg * 8));      aw1[0]=t.x;aw1[1]=t.y;aw1[2]=t.z;aw1[3]=t.w;
        t = __ldg((const float4*)(att_w + cg * 8 + 4));  aw1[4]=t.x;aw1[5]=t.y;aw1[6]=t.z;aw1[7]=t.w;
        t = __ldg((const float4*)(att_w + H + cg * 8));     aw2[0]=t.x;aw2[1]=t.y;aw2[2]=t.z;aw2[3]=t.w;
        t = __ldg((const float4*)(att_w + H + cg * 8 + 4)); aw2[4]=t.x;aw2[5]=t.y;aw2[6]=t.z;aw2[7]=t.w;
    }

    float p1[4], p2[4];
#pragma unroll
    for (int n = 0; n < 4; n++) {
        float s1 = 0.f, s2 = 0.f;
#pragma unroll
        for (int j = 0; j < 4; j++) {
            float a, b;
            unpack2(acc1[n][j], a, b);
            s1 += fmaxf(a + b1v[2 * j], 0.f) * aw1[2 * j]
                + fmaxf(b + b1v[2 * j + 1], 0.f) * aw1[2 * j + 1];
            unpack2(acc2[n][j], a, b);
            s2 += fmaxf(a + b2v[2 * j], 0.f) * aw2[2 * j]
                + fmaxf(b + b2v[2 * j + 1], 0.f) * aw2[2 * j + 1];
        }
        p1[n] = s1;
        p2[n] = s2;
    }

    // ---- cross-colgroup reduction via smem (reuse Xs) ----
    __syncthreads();
    float* red1 = Xs;           // [128 nodes][8 cg]
    float* red2 = Xs + 1024;
#pragma unroll
    for (int n = 0; n < 4; n++) {
        int nl = ng * 4 + n;
        red1[nl * 8 + cg] = p1[n];
        red2[nl * 8 + cg] = p2[n];
    }
    __syncthreads();

    if (tid < 128) {
        int node = tile + tid;
        if (node < N_NODES) {
            float s1 = 0.f, s2 = 0.f;
#pragma unroll
            for (int c = 0; c < 8; c++) { s1 += red1[tid * 8 + c]; s2 += red2[tid * 8 + c]; }
            g_s1[node] = s1;
            g_s2[node] = s2 + __ldg(att_b);
            g_rowsum[node] = 0.f;
        }
    }

    // ---- zero output SpMM region (d_out is poisoned) ----
    {
        float4 z = make_float4(0.f, 0.f, 0.f, 0.f);
        float4* op = (float4*)(out_part + (size_t)tile * H);
        int lim = N_NODES - tile;          // nodes valid in this tile
        if (lim > 128) lim = 128;
        int lim4 = lim * 16;               // float4s valid
#pragma unroll
        for (int i = 0; i < 8; i++) {
            int idx = tid + i * 256;
            if (idx < lim4) op[idx] = z;
        }
    }
}

// ------------------------------------------------------------------------
// Kernel 2: per-edge exp(att) + segment-sum of denominators
// ------------------------------------------------------------------------
__global__ __launch_bounds__(256)
void gat_edge_att_kernel(const int* __restrict__ edge_index) {
    int e = blockIdx.x * blockDim.x + threadIdx.x;
    if (e >= N_EDGES) return;
    int r = __ldg(edge_index + e);
    int c = __ldg(edge_index + N_EDGES + e);
    float ea = __expf(__ldg(g_s1 + r) + __ldg(g_s2 + c));
    g_expatt[e] = ea;
    atomicAdd(&g_rowsum[r], ea);
}

// ------------------------------------------------------------------------
// Kernel 3: per-edge value + SpMM scatter (16 threads/edge, float4 red).
// All 16 lanes recompute v from broadcast (same-address) loads — no shfl.
// ------------------------------------------------------------------------
__global__ __launch_bounds__(256)
void gat_edge_spmm_kernel(const int* __restrict__ edge_index,
                          const float* __restrict__ adj_values,
                          const float* __restrict__ embeds,
                          float* __restrict__ values,
                          float* __restrict__ out_part) {
    unsigned gid = blockIdx.x * blockDim.x + threadIdx.x;
    unsigned e = gid >> 4;
    if (e >= N_EDGES) return;
    unsigned sub = gid & 15u;

    int r = __ldg(edge_index + e);
    int c = __ldg(edge_index + N_EDGES + e);
    float ea = __ldg(g_expatt + e);
    float rs = __ldg(g_rowsum + r) + 1e-6f;
    float v = (ea / rs + RES * __ldg(adj_values + e)) * INV_1PRES;
    if (sub == 0) values[e] = v;

    float4 ev = __ldg((const float4*)(embeds + (size_t)c * H + sub * 4));
    float* dst = out_part + (size_t)r * H + sub * 4;
    asm volatile("red.global.add.v4.f32 [%0], {%1, %2, %3, %4};"
                 :: "l"(dst), "f"(ev.x * v), "f"(ev.y * v), "f"(ev.z * v), "f"(ev.w * v)
                 : "memory");
}

// ------------------------------------------------------------------------
extern "C" void kernel_launch(void* const* d_in, const int* in_sizes, int n_in,
                              void* d_out, int out_size) {
    const int*   edge_index = (const int*)d_in[0];
    const float* adj_values = (const float*)d_in[1];
    const float* embeds     = (const float*)d_in[2];
    const float* W1         = (const float*)d_in[3];
    const float* b1         = (const float*)d_in[4];
    const float* W2         = (const float*)d_in[5];
    const float* b2         = (const float*)d_in[6];
    const float* att_w      = (const float*)d_in[7];
    const float* att_b      = (const float*)d_in[8];

    float* values   = (float*)d_out;            // [E]
    float* out_part = (float*)d_out + N_EDGES;  // [N, H]

    static bool attr_done = false;
    if (!attr_done) {
        cudaFuncSetAttribute(gat_node_kernel,
                             cudaFuncAttributeMaxDynamicSharedMemorySize, 65536);
        attr_done = true;
    }

    gat_node_kernel<<<(N_NODES + 127) / 128, 256, 65536>>>(
        embeds, W1, b1, W2, b2, att_w, att_b, out_part);

    gat_edge_att_kernel<<<(N_EDGES + 255) / 256, 256>>>(edge_index);

    gat_edge_spmm_kernel<<<(N_EDGES * 16 + 255) / 256, 256>>>(
        edge_index, adj_values, embeds, values, out_part);
}